// round 10
// baseline (speedup 1.0000x reference)
#include <cuda_runtime.h>

#define THREADS 256
#define IT 4                      // i-rows per thread
#define I_TILE (THREADS * IT)     // 1024
#define J_TILE 64
#define MAXB 8192

__device__ double g_partial[MAXB];
__device__ int    g_done = 0;

__device__ __forceinline__ float fast_ex2(float x) {
    float r; asm("ex2.approx.f32 %0, %1;" : "=f"(r) : "f"(x)); return r;
}
__device__ __forceinline__ float fast_lg2(float x) {
    float r; asm("lg2.approx.f32 %0, %1;" : "=f"(r) : "f"(x)); return r;
}
// 2^( a XOR signbit(s) ) — XOR/AND in C++ so ptxas fuses one LOP3 feeding MUFU
__device__ __forceinline__ float ex2s(float a, float s) {
    unsigned u = __float_as_uint(a) ^ (__float_as_uint(s) & 0x80000000u);
    return fast_ex2(__uint_as_float(u));
}
// if (jx > ig) prod = fma(prod, e, prod)
__device__ __forceinline__ void fma_if_gt(float& prod, float e, int jx, int ig) {
    asm("{\n\t"
        ".reg .pred p;\n\t"
        "setp.gt.s32 p, %2, %3;\n\t"
        "@p fma.rn.f32 %0, %0, %1, %0;\n\t"
        "}" : "+f"(prod) : "f"(e), "r"(jx), "r"(ig));
}

// Pair {i,j}: logsig(D) = -ln2 * lg2(1 + 2^arg), arg = +-(pjs - pis).
// Identity: lg2(1+2^{-a}) = lg2(1+2^{a}) - a. Dense blocks accumulate
// lg2(1+2^a) for ALL pairs (no sign logic), then subtract the linear
// correction sum_{tj<ti} a = Spre[m] - m*pis using a target-sorted tile.
__global__ __launch_bounds__(THREADS, 4)
void rankloss_kernel(const float* __restrict__ P, const float* __restrict__ T,
                     float* __restrict__ out, int n, int NTI, int NTJ,
                     double inv_neg_count) {
    const int tid = threadIdx.x;
    const int nb  = gridDim.x;

    // decode linear block id -> (I, J) over upper-triangle band
    int b = blockIdx.x, I = 0, J = 0;
    {
        int rem = b;
        for (int ii = 0; ii < NTI; ++ii) {
            int jmin = (ii * I_TILE) / J_TILE;
            int cntI = NTJ - jmin;
            if (rem < cntI) { I = ii; J = jmin + rem; break; }
            rem -= cntI;
        }
    }
    const int I0 = I * I_TILE;
    const int J0 = J * J_TILE;
    const bool dense = (J0 >= I0 + I_TILE) && (J0 + J_TILE <= n) && (I0 + I_TILE <= n);

    __shared__ __align__(16) float st[J_TILE];    // tj   (sorted ascending)
    __shared__ __align__(16) float sp[J_TILE];    // pjs  (payload)
    __shared__ __align__(16) int   sx[J_TILE];    // orig index (payload, band)
    __shared__ float  spre[J_TILE + 1];           // prefix sums of sorted sp
    __shared__ double sred[THREADS];

    const float LOG2E = 1.4426950408889634f;
    const float PINF  = __int_as_float(0x7F800000);

    if (tid < J_TILE) {
        int jg = J0 + tid;
        if (jg < n) { st[tid] = T[jg]; sp[tid] = P[jg] * LOG2E; sx[tid] = jg; }
        else        { st[tid] = PINF;  sp[tid] = 0.0f; sx[tid] = (int)0x80000000; }
    }

    float pis[IT], nis[IT], tif[IT];
    int   igv[IT];
    #pragma unroll
    for (int r = 0; r < IT; ++r) {
        int ig = I0 + r * THREADS + tid;
        int g  = (ig < n) ? ig : 0;
        pis[r] = P[g] * LOG2E;
        nis[r] = -pis[r];
        tif[r] = T[g];
        igv[r] = ig;
    }
    __syncthreads();

    // Bitonic sort of the 64-entry tile by target (payloads sp, sx follow).
    for (int k = 2; k <= J_TILE; k <<= 1) {
        for (int half = k >> 1; half > 0; half >>= 1) {
            if (tid < J_TILE) {
                int partner = tid ^ half;
                if (partner > tid) {
                    bool up = ((tid & k) == 0);
                    float t1 = st[tid], t2 = st[partner];
                    if ((t1 > t2) == up) {
                        st[tid] = t2; st[partner] = t1;
                        float p1 = sp[tid], p2 = sp[partner];
                        sp[tid] = p2; sp[partner] = p1;
                        int x1 = sx[tid], x2 = sx[partner];
                        sx[tid] = x2; sx[partner] = x1;
                    }
                }
            }
            __syncthreads();
        }
    }
    if (tid == 0) {
        float run = 0.0f;
        spre[0] = 0.0f;
        for (int k = 0; k < J_TILE; ++k) { run += sp[k]; spre[k + 1] = run; }
    }
    __syncthreads();

    float acc = 0.0f;

    if (dense) {
        // m_r = #(tj < ti) via branchless binary search on sorted st
        int mI[IT];
        #pragma unroll
        for (int r = 0; r < IT; ++r) {
            int m = 0;
            #pragma unroll
            for (int step = 32; step >= 1; step >>= 1)
                if (st[m + step - 1] < tif[r]) m += step;
            if (m < J_TILE && st[m] < tif[r]) m++;   // unreachable; safety
            mI[r] = m;
        }

        #pragma unroll 1
        for (int j = 0; j < J_TILE; j += 8) {
            float4 v0 = *reinterpret_cast<const float4*>(&sp[j]);
            float4 v1 = *reinterpret_cast<const float4*>(&sp[j + 4]);
            float pj[8] = {v0.x, v0.y, v0.z, v0.w, v1.x, v1.y, v1.z, v1.w};
            float prod0 = 1.0f, prod1 = 1.0f, prod2 = 1.0f, prod3 = 1.0f;
            #pragma unroll
            for (int jj = 0; jj < 8; ++jj) {
                float e0 = fast_ex2(pj[jj] + nis[0]);
                float e1 = fast_ex2(pj[jj] + nis[1]);
                float e2 = fast_ex2(pj[jj] + nis[2]);
                float e3 = fast_ex2(pj[jj] + nis[3]);
                prod0 = fmaf(prod0, e0, prod0);
                prod1 = fmaf(prod1, e1, prod1);
                prod2 = fmaf(prod2, e2, prod2);
                prod3 = fmaf(prod3, e3, prod3);
            }
            acc += fast_lg2(prod0);
            acc += fast_lg2(prod1);
            acc += fast_lg2(prod2);
            acc += fast_lg2(prod3);
        }

        // linear correction: subtract sum_{tj<ti} (pjs - pis) per row
        #pragma unroll
        for (int r = 0; r < IT; ++r)
            acc -= spre[mI[r]] + (float)mI[r] * nis[r];
    } else {
        #pragma unroll 1
        for (int j = 0; j < J_TILE; j += 8) {
            float4 t0 = *reinterpret_cast<const float4*>(&st[j]);
            float4 t1 = *reinterpret_cast<const float4*>(&st[j + 4]);
            float4 q0 = *reinterpret_cast<const float4*>(&sp[j]);
            float4 q1 = *reinterpret_cast<const float4*>(&sp[j + 4]);
            int4   x0 = *reinterpret_cast<const int4*>(&sx[j]);
            int4   x1 = *reinterpret_cast<const int4*>(&sx[j + 4]);
            float tj[8] = {t0.x, t0.y, t0.z, t0.w, t1.x, t1.y, t1.z, t1.w};
            float pj[8] = {q0.x, q0.y, q0.z, q0.w, q1.x, q1.y, q1.z, q1.w};
            int   xj[8] = {x0.x, x0.y, x0.z, x0.w, x1.x, x1.y, x1.z, x1.w};
            float prod0 = 1.0f, prod1 = 1.0f, prod2 = 1.0f, prod3 = 1.0f;
            #pragma unroll
            for (int jj = 0; jj < 8; ++jj) {
                float s0 = tif[0] - tj[jj], a0 = pis[0] - pj[jj];
                float s1 = tif[1] - tj[jj], a1 = pis[1] - pj[jj];
                float s2 = tif[2] - tj[jj], a2 = pis[2] - pj[jj];
                float s3 = tif[3] - tj[jj], a3 = pis[3] - pj[jj];
                float e0 = ex2s(a0, s0);
                float e1 = ex2s(a1, s1);
                float e2 = ex2s(a2, s2);
                float e3 = ex2s(a3, s3);
                fma_if_gt(prod0, e0, xj[jj], igv[0]);
                fma_if_gt(prod1, e1, xj[jj], igv[1]);
                fma_if_gt(prod2, e2, xj[jj], igv[2]);
                fma_if_gt(prod3, e3, xj[jj], igv[3]);
            }
            acc += fast_lg2(prod0);
            acc += fast_lg2(prod1);
            acc += fast_lg2(prod2);
            acc += fast_lg2(prod3);
        }
    }

    // block reduction (fixed order -> deterministic)
    sred[tid] = (double)acc;
    __syncthreads();
    #pragma unroll
    for (int s = THREADS / 2; s > 0; s >>= 1) {
        if (tid < s) sred[tid] += sred[tid + s];
        __syncthreads();
    }
    if (tid == 0) g_partial[blockIdx.x] = sred[0];

    // last-block finalize (fixed order -> deterministic)
    __shared__ int is_last;
    if (tid == 0) {
        __threadfence();
        int prev = atomicAdd(&g_done, 1);
        is_last = (prev == nb - 1) ? 1 : 0;
    }
    __syncthreads();
    if (is_last) {
        __threadfence();
        double s = 0.0;
        for (int i = tid; i < nb; i += THREADS) s += g_partial[i];
        sred[tid] = s;
        __syncthreads();
        #pragma unroll
        for (int k = THREADS / 2; k > 0; k >>= 1) {
            if (tid < k) sred[tid] += sred[tid + k];
            __syncthreads();
        }
        if (tid == 0) {
            out[0] = (float)(sred[0] * inv_neg_count);
            g_done = 0;   // reset for next graph replay
        }
    }
}

extern "C" void kernel_launch(void* const* d_in, const int* in_sizes, int n_in,
                              void* d_out, int out_size) {
    const float* predictions = (const float*)d_in[0];
    const float* targets     = (const float*)d_in[1];
    const int n = in_sizes[0];

    const int NTI = (n + I_TILE - 1) / I_TILE;   // 8 for n=8192
    const int NTJ = (n + J_TILE - 1) / J_TILE;   // 128
    int nb = 0;
    for (int ii = 0; ii < NTI; ++ii) {
        int jmin = (ii * I_TILE) / J_TILE;
        nb += NTJ - jmin;                        // 576 for n=8192
    }
    const double count = 0.5 * (double)n * (double)(n - 1);
    const double inv_neg_count = -0.6931471805599453 / count;

    rankloss_kernel<<<nb, THREADS>>>(predictions, targets, (float*)d_out,
                                     n, NTI, NTJ, inv_neg_count);
}

// round 12
// speedup vs baseline: 1.3605x; 1.3605x over previous
#include <cuda_runtime.h>
#include <cuda_fp16.h>

#define THREADS 256
#define IT 4                      // i-rows per thread
#define I_TILE (THREADS * IT)     // 1024
#define J_TILE 64
#define MAXB 8192

__device__ double g_partial[MAXB];
__device__ int    g_done = 0;

__device__ __forceinline__ float fast_lg2(float x) {
    float r; asm("lg2.approx.f32 %0, %1;" : "=f"(r) : "f"(x)); return r;
}
// packed 2^x on two fp16 halves — ONE MUFU op for 2 pairs
__device__ __forceinline__ unsigned ex2_h2(unsigned u) {
    unsigned r; asm("ex2.approx.f16x2 %0, %1;" : "=r"(r) : "r"(u)); return r;
}
// arg = a XOR (signbits of s) per fp16 half: one LOP3 (immLut 0x78 = a^(b&c))
__device__ __forceinline__ unsigned sign2(unsigned a, unsigned s) {
    unsigned r;
    asm("lop3.b32 %0, %1, %2, 0x80008000, 0x78;" : "=r"(r) : "r"(a), "r"(s));
    return r;
}
__device__ __forceinline__ unsigned h2bits(__half2 h) {
    return *reinterpret_cast<unsigned*>(&h);
}
__device__ __forceinline__ __half2 bits2h(unsigned u) {
    return *reinterpret_cast<__half2*>(&u);
}

// Pair {i,j}: if ti<tj contribute logsig(pi-pj) = -ln2*lg2(1+2^(pjs-pis)),
// if ti>tj the mirrored arg. Orientation: a = pjs - pis, s = tj - ti;
//   s > 0 (ti<tj): arg = a        (pjs - pis)  ✓
//   s < 0 (ti>tj): arg = a^sign = pis - pjs    ✓
// All blocks run a full IxJ cross. Band blocks (J-range inside I-range) see
// each unordered pair twice (identical contribution both ways) plus diagonal
// (exactly 1.0 each): partial = 0.5*(sum - jcount). Count analytic: n(n-1)/2.
__global__ __launch_bounds__(THREADS, 4)
void rankloss_kernel(const float* __restrict__ P, const float* __restrict__ T,
                     float* __restrict__ out, int n, int NTI, int NTJ,
                     double inv_neg_count) {
    const int tid = threadIdx.x;
    const int nb  = gridDim.x;

    // decode linear block id -> (I, J) over upper-triangle band
    int b = blockIdx.x, I = 0, J = 0;
    {
        int rem = b;
        for (int ii = 0; ii < NTI; ++ii) {
            int jmin = (ii * I_TILE) / J_TILE;
            int cntI = NTJ - jmin;
            if (rem < cntI) { I = ii; J = jmin + rem; break; }
            rem -= cntI;
        }
    }
    const int I0 = I * I_TILE;
    const int J0 = J * J_TILE;
    const bool band = (J0 < I0 + I_TILE);   // J-range inside I-range: weight 1/2

    __shared__ uint2  sjv[J_TILE];   // .x = half2(tj,tj), .y = half2(pjs,pjs)
    __shared__ double sred[THREADS];

    const float LOG2E = 1.4426950408889634f;
    const float INF   = __int_as_float(0x7F800000);

    if (tid < J_TILE) {
        int jg = J0 + tid;
        float tj, pj;
        if (jg < n) { tj = T[jg]; pj = P[jg] * LOG2E; }
        else        { tj = INF;   pj = -INF; }   // s=+inf (no flip), a=-inf -> e=0
        sjv[tid] = make_uint2(h2bits(__floats2half2_rn(tj, tj)),
                              h2bits(__floats2half2_rn(pj, pj)));
    }

    float tiv[IT], piv[IT];
    #pragma unroll
    for (int r = 0; r < IT; ++r) {
        int ig = I0 + r * THREADS + tid;
        if (ig < n) { tiv[r] = T[ig]; piv[r] = P[ig] * LOG2E; }
        else        { tiv[r] = -INF;  piv[r] = INF; }  // s=+inf, a=-inf -> e=0
    }
    const unsigned ti01 = h2bits(__floats2half2_rn(tiv[0], tiv[1]));
    const unsigned ti23 = h2bits(__floats2half2_rn(tiv[2], tiv[3]));
    const unsigned pi01 = h2bits(__floats2half2_rn(piv[0], piv[1]));
    const unsigned pi23 = h2bits(__floats2half2_rn(piv[2], piv[3]));
    __syncthreads();

    float acc = 0.0f;

    #pragma unroll 1
    for (int j = 0; j < J_TILE; j += 8) {
        float prod0 = 1.0f, prod1 = 1.0f, prod2 = 1.0f, prod3 = 1.0f;
        #pragma unroll
        for (int jj = 0; jj < 8; ++jj) {
            uint2 v = sjv[j + jj];             // one broadcast LDS.64
            // s = tj - ti  (sign selects orientation)
            unsigned s01 = h2bits(__hsub2(bits2h(v.x), bits2h(ti01)));
            unsigned s23 = h2bits(__hsub2(bits2h(v.x), bits2h(ti23)));
            // a = pjs - pis
            unsigned a01 = h2bits(__hsub2(bits2h(v.y), bits2h(pi01)));
            unsigned a23 = h2bits(__hsub2(bits2h(v.y), bits2h(pi23)));
            unsigned e01 = ex2_h2(sign2(a01, s01));
            unsigned e23 = ex2_h2(sign2(a23, s23));
            float2 f01 = __half22float2(bits2h(e01));
            float2 f23 = __half22float2(bits2h(e23));
            prod0 = fmaf(prod0, f01.x, prod0);
            prod1 = fmaf(prod1, f01.y, prod1);
            prod2 = fmaf(prod2, f23.x, prod2);
            prod3 = fmaf(prod3, f23.y, prod3);
        }
        acc += fast_lg2(prod0);
        acc += fast_lg2(prod1);
        acc += fast_lg2(prod2);
        acc += fast_lg2(prod3);
    }

    // block reduction (fixed order -> deterministic)
    sred[tid] = (double)acc;
    __syncthreads();
    #pragma unroll
    for (int s = THREADS / 2; s > 0; s >>= 1) {
        if (tid < s) sred[tid] += sred[tid + s];
        __syncthreads();
    }
    if (tid == 0) {
        double bsum = sred[0];
        if (band) {
            int jcount = min(J_TILE, n - J0);       // diagonal elements hit
            bsum = 0.5 * (bsum - (double)jcount);   // remove diag, undo x2
        }
        g_partial[blockIdx.x] = bsum;
    }

    // last-block finalize (fixed order -> deterministic)
    __shared__ int is_last;
    if (tid == 0) {
        __threadfence();
        int prev = atomicAdd(&g_done, 1);
        is_last = (prev == nb - 1) ? 1 : 0;
    }
    __syncthreads();
    if (is_last) {
        __threadfence();
        double s = 0.0;
        for (int i = tid; i < nb; i += THREADS) s += g_partial[i];
        sred[tid] = s;
        __syncthreads();
        #pragma unroll
        for (int k = THREADS / 2; k > 0; k >>= 1) {
            if (tid < k) sred[tid] += sred[tid + k];
            __syncthreads();
        }
        if (tid == 0) {
            out[0] = (float)(sred[0] * inv_neg_count);
            g_done = 0;   // reset for next graph replay
        }
    }
}

extern "C" void kernel_launch(void* const* d_in, const int* in_sizes, int n_in,
                              void* d_out, int out_size) {
    const float* predictions = (const float*)d_in[0];
    const float* targets     = (const float*)d_in[1];
    const int n = in_sizes[0];

    const int NTI = (n + I_TILE - 1) / I_TILE;   // 8 for n=8192
    const int NTJ = (n + J_TILE - 1) / J_TILE;   // 128
    int nb = 0;
    for (int ii = 0; ii < NTI; ++ii) {
        int jmin = (ii * I_TILE) / J_TILE;
        nb += NTJ - jmin;                        // 576 for n=8192
    }
    const double count = 0.5 * (double)n * (double)(n - 1);
    const double inv_neg_count = -0.6931471805599453 / count;

    rankloss_kernel<<<nb, THREADS>>>(predictions, targets, (float*)d_out,
                                     n, NTI, NTJ, inv_neg_count);
}